// round 10
// baseline (speedup 1.0000x reference)
#include <cuda_runtime.h>
#include <cstdint>

// Psi11t flow force: F = 2*t*c0 * ( s x (Fs*b + Fbs) )
//   Fs = nbr4(s), b = s.Fs, Fbs = nbr4(s*b). Periodic 512x512, B=32, S=3.
// Register-marching stencil + cp.async smem row-ring (4 slots, distance-2
// prefetch). 128 threads own the full Y=512 ring (float4/thread), march
// XCHUNK=16 x-rows. launch_bounds(128,5) -> 5 blocks/SM for issue bandwidth.

#define MASK 511
#define XCHUNK 16
#define NTH 128

__device__ __forceinline__ float4 operator+(float4 a, float4 b) {
    return make_float4(a.x + b.x, a.y + b.y, a.z + b.z, a.w + b.w);
}
__device__ __forceinline__ float4 fma4(float4 a, float4 b, float4 c) {
    return make_float4(fmaf(a.x, b.x, c.x), fmaf(a.y, b.y, c.y),
                       fmaf(a.z, b.z, c.z), fmaf(a.w, b.w, c.w));
}
__device__ __forceinline__ float4 crossm(float4 a, float4 b, float4 c, float4 d) {
    return make_float4(fmaf(a.x, b.x, -(c.x * d.x)), fmaf(a.y, b.y, -(c.y * d.y)),
                       fmaf(a.z, b.z, -(c.z * d.z)), fmaf(a.w, b.w, -(c.w * d.w)));
}
__device__ __forceinline__ float4 ymv(float4 a, float lw) {
    return make_float4(lw, a.x, a.y, a.z);
}
__device__ __forceinline__ float4 ypv(float4 a, float rx) {
    return make_float4(a.y, a.z, a.w, rx);
}
__device__ __forceinline__ float4 scale4(float k, float4 a) {
    return make_float4(k * a.x, k * a.y, k * a.z, k * a.w);
}
__device__ __forceinline__ void cpa16(float* smem_dst, const float* g) {
    uint32_t sa = (uint32_t)__cvta_generic_to_shared(smem_dst);
    asm volatile("cp.async.cg.shared.global [%0], [%1], 16;" :: "r"(sa), "l"(g));
}
__device__ __forceinline__ void cpa_commit() {
    asm volatile("cp.async.commit_group;");
}
__device__ __forceinline__ void cpa_wait2() {
    asm volatile("cp.async.wait_group 2;");
}

__global__ __launch_bounds__(NTH, 5) void psi11t_kernel(
    const float* __restrict__ s,
    const float* __restrict__ tt,
    const float* __restrict__ c0,
    float* __restrict__ out)
{
    __shared__ float ring[4][3][512];       // 24576 B: 4-row-slot ring
    __shared__ float bw[2][NTH], bx[2][NTH];

    const int bb = blockIdx.y;
    const int x0 = blockIdx.x * XCHUNK;
    const int t  = threadIdx.x;
    const int tm = (t - 1) & (NTH - 1);
    const int tp = (t + 1) & (NTH - 1);
    const long base = (long)bb * (3L << 18);
    const float* sb = s + base;
    const int yo  = 4 * t;
    const int ym1 = (yo - 1) & MASK;
    const int yp4 = (yo + 4) & MASK;

    const float coeff = 2.0f * tt[0] * c0[0];

    // ---- issue cp.async for rows x0+2, x0+3 first (max overlap) ----
    {
        const int r2 = (x0 + 2) & MASK, r3 = (x0 + 3) & MASK;
        #pragma unroll
        for (int c = 0; c < 3; ++c)
            cpa16(&ring[(x0 + 2) & 3][c][yo], sb + ((long)c << 18) + ((long)r2 << 9) + yo);
        cpa_commit();
        #pragma unroll
        for (int c = 0; c < 3; ++c)
            cpa16(&ring[(x0 + 3) & 3][c][yo], sb + ((long)c << 18) + ((long)r3 << 9) + yo);
        cpa_commit();
    }

    // Persistent state: 3 s-rows, 2 b-rows, boundary scalars.
    float4 sP[3], sC[3], sN[3];
    float4 bP, bC;
    float  sClw[3], sCrx[3], sNlw[3], sNrx[3];
    float  bClw, bCrx;

    // ---------------- Prologue: rows x0-2 .. x0+1 (direct LDG) ----------------
    {
        const int rA = (x0 - 2) & MASK, rP = (x0 - 1) & MASK;
        const int rC = x0, rN = x0 + 1;
        float4 sA[3];
        float plw[3], prx[3];
        #pragma unroll
        for (int c = 0; c < 3; ++c) {
            const float* cp = sb + ((long)c << 18);
            sA[c] = *(const float4*)(cp + ((long)rA << 9) + yo);
            sP[c] = *(const float4*)(cp + ((long)rP << 9) + yo);
            sC[c] = *(const float4*)(cp + ((long)rC << 9) + yo);
            sN[c] = *(const float4*)(cp + ((long)rN << 9) + yo);
            plw[c]  = cp[((long)rP << 9) + ym1];  prx[c]  = cp[((long)rP << 9) + yp4];
            sClw[c] = cp[((long)rC << 9) + ym1];  sCrx[c] = cp[((long)rC << 9) + yp4];
            sNlw[c] = cp[((long)rN << 9) + ym1];  sNrx[c] = cp[((long)rN << 9) + yp4];
        }

        // bP = sP . (sA + sC + ym(sP) + yp(sP))
        bP = make_float4(0.f, 0.f, 0.f, 0.f);
        #pragma unroll
        for (int c = 0; c < 3; ++c)
            bP = fma4(sP[c], sA[c] + sC[c] + ymv(sP[c], plw[c]) + ypv(sP[c], prx[c]), bP);

        // bC = sC . (sP + sN + ym(sC) + yp(sC))
        bC = make_float4(0.f, 0.f, 0.f, 0.f);
        #pragma unroll
        for (int c = 0; c < 3; ++c)
            bC = fma4(sC[c], sP[c] + sN[c] + ymv(sC[c], sClw[c]) + ypv(sC[c], sCrx[c]), bC);

        // exchange bC bounds via buffer 1 (main loop starts on buffer 0)
        bw[1][t] = bC.w; bx[1][t] = bC.x;
        __syncthreads();
        bClw = bw[1][tm]; bCrx = bx[1][tp];
    }

    // ---------------- Main loop: output rows x0 .. x0+XCHUNK-1 ----------------
    #pragma unroll 2
    for (int i = 0; i < XCHUNK; ++i) {
        const int x = x0 + i;
        const int p = i & 1;

        // 1. prefetch row x+4 into slot (x+4)&3
        {
            const int r4 = (x + 4) & MASK;
            #pragma unroll
            for (int c = 0; c < 3; ++c)
                cpa16(&ring[(x + 4) & 3][c][yo],
                      sb + ((long)c << 18) + ((long)r4 << 9) + yo);
            cpa_commit();
        }

        // 2. wait for row x+2 (committed 2 groups ago), read own vector
        cpa_wait2();
        const int slot2 = (x + 2) & 3;
        float4 sN2[3];
        #pragma unroll
        for (int c = 0; c < 3; ++c)
            sN2[c] = *(const float4*)&ring[slot2][c][yo];

        // 3. bN = sN . (sC + sN2 + ym(sN) + yp(sN))   [b at row x+1]
        float4 bN = make_float4(0.f, 0.f, 0.f, 0.f);
        #pragma unroll
        for (int c = 0; c < 3; ++c)
            bN = fma4(sN[c], sC[c] + sN2[c] + ymv(sN[c], sNlw[c]) + ypv(sN[c], sNrx[c]), bN);

        // 4. publish bN bounds
        bw[p][t] = bN.w; bx[p][t] = bN.x;
        __syncthreads();

        // 5. post-sync reads: bN bounds + row x+2 bounds (neighbor cp.async data)
        const float bNlw = bw[p][tm], bNrx = bx[p][tp];
        float n2lw[3], n2rx[3];
        #pragma unroll
        for (int c = 0; c < 3; ++c) {
            n2lw[c] = ring[slot2][c][ym1];
            n2rx[c] = ring[slot2][c][yp4];
        }

        // 6. F at row x
        const float4 bym = ymv(bC, bClw);
        const float4 byp = ypv(bC, bCrx);
        float4 Fv[3];
        #pragma unroll
        for (int c = 0; c < 3; ++c) {
            const float4 ymc = ymv(sC[c], sClw[c]);
            const float4 ypc = ypv(sC[c], sCrx[c]);
            const float4 Fs  = sP[c] + sN[c] + ymc + ypc;
            const float4 Fbs = fma4(sP[c], bP,
                               fma4(sN[c], bN,
                               fma4(ymc, bym,
                                    make_float4(ypc.x * byp.x, ypc.y * byp.y,
                                                ypc.z * byp.z, ypc.w * byp.w))));
            Fv[c] = fma4(Fs, bC, Fbs);
        }

        float* op = out + base + (((long)x) << 9) + yo;
        __stcs((float4*)(op),              scale4(coeff, crossm(sC[1], Fv[2], sC[2], Fv[1])));
        __stcs((float4*)(op + (1L << 18)), scale4(coeff, crossm(sC[2], Fv[0], sC[0], Fv[2])));
        __stcs((float4*)(op + (2L << 18)), scale4(coeff, crossm(sC[0], Fv[1], sC[1], Fv[0])));

        // 7. rotate pipeline (register renames under unroll 2)
        #pragma unroll
        for (int c = 0; c < 3; ++c) {
            sP[c] = sC[c]; sC[c] = sN[c]; sN[c] = sN2[c];
            sClw[c] = sNlw[c]; sCrx[c] = sNrx[c];
            sNlw[c] = n2lw[c]; sNrx[c] = n2rx[c];
        }
        bP = bC; bC = bN;
        bClw = bNlw; bCrx = bNrx;
    }
}

extern "C" void kernel_launch(void* const* d_in, const int* in_sizes, int n_in,
                              void* d_out, int out_size)
{
    const float* s  = (const float*)d_in[0];
    const float* t  = (const float*)d_in[1];
    const float* c0 = (const float*)d_in[2];
    float* out = (float*)d_out;

    dim3 grid(512 / XCHUNK, 32);   // 32 x-strips * 32 batches = 1024 blocks
    psi11t_kernel<<<grid, NTH>>>(s, t, c0, out);
}

// round 11
// speedup vs baseline: 1.0968x; 1.0968x over previous
#include <cuda_runtime.h>
#include <cstdint>

// Psi11t flow force: F = 2*t*c0 * ( s x (Fs*b + Fbs) )
//   Fs = nbr4(s), b = s.Fs, Fbs = nbr4(s*b). Periodic 512x512, B=32, S=3.
// Register-marching stencil + cp.async smem row-ring, 6 slots, DISTANCE-3
// prefetch (3 groups in flight). 128 threads own the full Y=512 ring
// (float4/thread), march XCHUNK=32 x-rows (512 blocks, single wave).

#define MASK 511
#define XCHUNK 32
#define NTH 128
#define NSLOT 6

__device__ __forceinline__ float4 operator+(float4 a, float4 b) {
    return make_float4(a.x + b.x, a.y + b.y, a.z + b.z, a.w + b.w);
}
__device__ __forceinline__ float4 fma4(float4 a, float4 b, float4 c) {
    return make_float4(fmaf(a.x, b.x, c.x), fmaf(a.y, b.y, c.y),
                       fmaf(a.z, b.z, c.z), fmaf(a.w, b.w, c.w));
}
__device__ __forceinline__ float4 crossm(float4 a, float4 b, float4 c, float4 d) {
    return make_float4(fmaf(a.x, b.x, -(c.x * d.x)), fmaf(a.y, b.y, -(c.y * d.y)),
                       fmaf(a.z, b.z, -(c.z * d.z)), fmaf(a.w, b.w, -(c.w * d.w)));
}
__device__ __forceinline__ float4 ymv(float4 a, float lw) {
    return make_float4(lw, a.x, a.y, a.z);
}
__device__ __forceinline__ float4 ypv(float4 a, float rx) {
    return make_float4(a.y, a.z, a.w, rx);
}
__device__ __forceinline__ float4 scale4(float k, float4 a) {
    return make_float4(k * a.x, k * a.y, k * a.z, k * a.w);
}
__device__ __forceinline__ void cpa16(float* smem_dst, const float* g) {
    uint32_t sa = (uint32_t)__cvta_generic_to_shared(smem_dst);
    asm volatile("cp.async.cg.shared.global [%0], [%1], 16;" :: "r"(sa), "l"(g));
}
__device__ __forceinline__ void cpa_commit() {
    asm volatile("cp.async.commit_group;");
}
__device__ __forceinline__ void cpa_wait3() {
    asm volatile("cp.async.wait_group 3;");
}

__global__ __launch_bounds__(NTH) void psi11t_kernel(
    const float* __restrict__ s,
    const float* __restrict__ tt,
    const float* __restrict__ c0,
    float* __restrict__ out)
{
    __shared__ float ring[NSLOT][3][512];   // 36864 B: 6-row-slot ring
    __shared__ float bw[2][NTH], bx[2][NTH];

    const int bb = blockIdx.y;
    const int x0 = blockIdx.x * XCHUNK;
    const int t  = threadIdx.x;
    const int tm = (t - 1) & (NTH - 1);
    const int tp = (t + 1) & (NTH - 1);
    const long base = (long)bb * (3L << 18);
    const float* sb = s + base;
    const int yo  = 4 * t;
    const int ym1 = (yo - 1) & MASK;
    const int yp4 = (yo + 4) & MASK;

    const float coeff = 2.0f * tt[0] * c0[0];

    // ---- issue cp.async for rows x0+2 .. x0+4 (3 groups, max overlap) ----
    #pragma unroll
    for (int k = 2; k <= 4; ++k) {
        const int r = (x0 + k) & MASK;
        #pragma unroll
        for (int c = 0; c < 3; ++c)
            cpa16(&ring[(x0 + k) % NSLOT][c][yo],
                  sb + ((long)c << 18) + ((long)r << 9) + yo);
        cpa_commit();
    }

    // Persistent state: 3 s-rows, 2 b-rows, boundary scalars.
    float4 sP[3], sC[3], sN[3];
    float4 bP, bC;
    float  sClw[3], sCrx[3], sNlw[3], sNrx[3];
    float  bClw, bCrx;

    // ---------------- Prologue: rows x0-2 .. x0+1 (direct LDG) ----------------
    {
        const int rA = (x0 - 2) & MASK, rP = (x0 - 1) & MASK;
        const int rC = x0, rN = x0 + 1;
        float4 sA[3];
        float plw[3], prx[3];
        #pragma unroll
        for (int c = 0; c < 3; ++c) {
            const float* cp = sb + ((long)c << 18);
            sA[c] = *(const float4*)(cp + ((long)rA << 9) + yo);
            sP[c] = *(const float4*)(cp + ((long)rP << 9) + yo);
            sC[c] = *(const float4*)(cp + ((long)rC << 9) + yo);
            sN[c] = *(const float4*)(cp + ((long)rN << 9) + yo);
            plw[c]  = cp[((long)rP << 9) + ym1];  prx[c]  = cp[((long)rP << 9) + yp4];
            sClw[c] = cp[((long)rC << 9) + ym1];  sCrx[c] = cp[((long)rC << 9) + yp4];
            sNlw[c] = cp[((long)rN << 9) + ym1];  sNrx[c] = cp[((long)rN << 9) + yp4];
        }

        // bP = sP . (sA + sC + ym(sP) + yp(sP))
        bP = make_float4(0.f, 0.f, 0.f, 0.f);
        #pragma unroll
        for (int c = 0; c < 3; ++c)
            bP = fma4(sP[c], sA[c] + sC[c] + ymv(sP[c], plw[c]) + ypv(sP[c], prx[c]), bP);

        // bC = sC . (sP + sN + ym(sC) + yp(sC))
        bC = make_float4(0.f, 0.f, 0.f, 0.f);
        #pragma unroll
        for (int c = 0; c < 3; ++c)
            bC = fma4(sC[c], sP[c] + sN[c] + ymv(sC[c], sClw[c]) + ypv(sC[c], sCrx[c]), bC);

        // exchange bC bounds via buffer 1 (main loop starts on buffer 0)
        bw[1][t] = bC.w; bx[1][t] = bC.x;
        __syncthreads();
        bClw = bw[1][tm]; bCrx = bx[1][tp];
    }

    // ---------------- Main loop: output rows x0 .. x0+XCHUNK-1 ----------------
    #pragma unroll 2
    for (int i = 0; i < XCHUNK; ++i) {
        const int x = x0 + i;
        const int p = i & 1;

        // 1. prefetch row x+5 into slot (x+5)%NSLOT (slot's old row x-1 was
        //    fully consumed 3 barriers ago)
        {
            const int r5 = (x + 5) & MASK;
            #pragma unroll
            for (int c = 0; c < 3; ++c)
                cpa16(&ring[(x + 5) % NSLOT][c][yo],
                      sb + ((long)c << 18) + ((long)r5 << 9) + yo);
            cpa_commit();
        }

        // 2. wait until only 3 groups pending -> row x+2 landed; read own vector
        cpa_wait3();
        const int slot2 = (x + 2) % NSLOT;
        float4 sN2[3];
        #pragma unroll
        for (int c = 0; c < 3; ++c)
            sN2[c] = *(const float4*)&ring[slot2][c][yo];

        // 3. bN = sN . (sC + sN2 + ym(sN) + yp(sN))   [b at row x+1]
        float4 bN = make_float4(0.f, 0.f, 0.f, 0.f);
        #pragma unroll
        for (int c = 0; c < 3; ++c)
            bN = fma4(sN[c], sC[c] + sN2[c] + ymv(sN[c], sNlw[c]) + ypv(sN[c], sNrx[c]), bN);

        // 4. publish bN bounds
        bw[p][t] = bN.w; bx[p][t] = bN.x;
        __syncthreads();

        // 5. post-sync reads: bN bounds + row x+2 bounds (neighbor cp.async data)
        const float bNlw = bw[p][tm], bNrx = bx[p][tp];
        float n2lw[3], n2rx[3];
        #pragma unroll
        for (int c = 0; c < 3; ++c) {
            n2lw[c] = ring[slot2][c][ym1];
            n2rx[c] = ring[slot2][c][yp4];
        }

        // 6. F at row x
        const float4 bym = ymv(bC, bClw);
        const float4 byp = ypv(bC, bCrx);
        float4 Fv[3];
        #pragma unroll
        for (int c = 0; c < 3; ++c) {
            const float4 ymc = ymv(sC[c], sClw[c]);
            const float4 ypc = ypv(sC[c], sCrx[c]);
            const float4 Fs  = sP[c] + sN[c] + ymc + ypc;
            const float4 Fbs = fma4(sP[c], bP,
                               fma4(sN[c], bN,
                               fma4(ymc, bym,
                                    make_float4(ypc.x * byp.x, ypc.y * byp.y,
                                                ypc.z * byp.z, ypc.w * byp.w))));
            Fv[c] = fma4(Fs, bC, Fbs);
        }

        float* op = out + base + (((long)x) << 9) + yo;
        __stcs((float4*)(op),              scale4(coeff, crossm(sC[1], Fv[2], sC[2], Fv[1])));
        __stcs((float4*)(op + (1L << 18)), scale4(coeff, crossm(sC[2], Fv[0], sC[0], Fv[2])));
        __stcs((float4*)(op + (2L << 18)), scale4(coeff, crossm(sC[0], Fv[1], sC[1], Fv[0])));

        // 7. rotate pipeline (register renames under unroll 2)
        #pragma unroll
        for (int c = 0; c < 3; ++c) {
            sP[c] = sC[c]; sC[c] = sN[c]; sN[c] = sN2[c];
            sClw[c] = sNlw[c]; sCrx[c] = sNrx[c];
            sNlw[c] = n2lw[c]; sNrx[c] = n2rx[c];
        }
        bP = bC; bC = bN;
        bClw = bNlw; bCrx = bNrx;
    }
}

extern "C" void kernel_launch(void* const* d_in, const int* in_sizes, int n_in,
                              void* d_out, int out_size)
{
    const float* s  = (const float*)d_in[0];
    const float* t  = (const float*)d_in[1];
    const float* c0 = (const float*)d_in[2];
    float* out = (float*)d_out;

    dim3 grid(512 / XCHUNK, 32);   // 16 x-strips * 32 batches = 512 blocks
    psi11t_kernel<<<grid, NTH>>>(s, t, c0, out);
}

// round 12
// speedup vs baseline: 1.1157x; 1.0172x over previous
#include <cuda_runtime.h>
#include <cstdint>

// Psi11t flow force: F = 2*t*c0 * ( s x (Fs*b + Fbs) )
//   Fs = nbr4(s), b = s.Fs, Fbs = nbr4(s*b). Periodic 512x512, B=32, S=3.
// Register-marching stencil + cp.async smem row-ring (6 slots), TWO rows per
// iteration with ONE barrier: pre-barrier {bN, F(x)}, post-barrier {bN2,
// F(x+1)}. bN2 edge scalars recomputed per-thread from ring halo (no 2nd
// exchange). 128 threads own Y=512 (float4/thread), XCHUNK=32, 512 blocks.

#define MASK 511
#define XCHUNK 32
#define NTH 128
#define NSLOT 6

__device__ __forceinline__ float4 operator+(float4 a, float4 b) {
    return make_float4(a.x + b.x, a.y + b.y, a.z + b.z, a.w + b.w);
}
__device__ __forceinline__ float4 fma4(float4 a, float4 b, float4 c) {
    return make_float4(fmaf(a.x, b.x, c.x), fmaf(a.y, b.y, c.y),
                       fmaf(a.z, b.z, c.z), fmaf(a.w, b.w, c.w));
}
__device__ __forceinline__ float4 crossm(float4 a, float4 b, float4 c, float4 d) {
    return make_float4(fmaf(a.x, b.x, -(c.x * d.x)), fmaf(a.y, b.y, -(c.y * d.y)),
                       fmaf(a.z, b.z, -(c.z * d.z)), fmaf(a.w, b.w, -(c.w * d.w)));
}
__device__ __forceinline__ float4 ymv(float4 a, float lw) {
    return make_float4(lw, a.x, a.y, a.z);
}
__device__ __forceinline__ float4 ypv(float4 a, float rx) {
    return make_float4(a.y, a.z, a.w, rx);
}
__device__ __forceinline__ float4 scale4(float k, float4 a) {
    return make_float4(k * a.x, k * a.y, k * a.z, k * a.w);
}
__device__ __forceinline__ void cpa16(float* smem_dst, const float* g) {
    uint32_t sa = (uint32_t)__cvta_generic_to_shared(smem_dst);
    asm volatile("cp.async.cg.shared.global [%0], [%1], 16;" :: "r"(sa), "l"(g));
}
__device__ __forceinline__ void cpa_commit() {
    asm volatile("cp.async.commit_group;");
}
__device__ __forceinline__ void cpa_wait1() {
    asm volatile("cp.async.wait_group 1;");
}

__global__ __launch_bounds__(NTH, 4) void psi11t_kernel(
    const float* __restrict__ s,
    const float* __restrict__ tt,
    const float* __restrict__ c0,
    float* __restrict__ out)
{
    __shared__ float ring[NSLOT][3][512];   // 36864 B
    __shared__ float bw[2][NTH], bx[2][NTH];

    const int bb = blockIdx.y;
    const int x0 = blockIdx.x * XCHUNK;
    const int t  = threadIdx.x;
    const int tm = (t - 1) & (NTH - 1);
    const int tp = (t + 1) & (NTH - 1);
    const long base = (long)bb * (3L << 18);
    const float* sb = s + base;
    const int yo  = 4 * t;
    const int ym1 = (yo - 1) & MASK;
    const int ym2 = (yo - 2) & MASK;
    const int yp4 = (yo + 4) & MASK;
    const int yp5 = (yo + 5) & MASK;

    const float coeff = 2.0f * tt[0] * c0[0];

    // ---- prologue prefetch: rows x0+2, x0+3 as ONE group ----
    {
        const int r2 = (x0 + 2) & MASK, r3 = (x0 + 3) & MASK;
        #pragma unroll
        for (int c = 0; c < 3; ++c) {
            cpa16(&ring[(x0 + 2) % NSLOT][c][yo], sb + ((long)c << 18) + ((long)r2 << 9) + yo);
            cpa16(&ring[(x0 + 3) % NSLOT][c][yo], sb + ((long)c << 18) + ((long)r3 << 9) + yo);
        }
        cpa_commit();
    }

    // Persistent: s rows x-1,x,x+1; b rows x-1,x; bounds.
    float4 sP[3], sC[3], sN[3];
    float4 bP, bC;
    float  sClw[3], sCrx[3], sNlw[3], sNrx[3];
    float  bClw, bCrx;

    // ---------------- Prologue compute: rows x0-2 .. x0+1 (direct LDG) -------
    {
        const int rA = (x0 - 2) & MASK, rP = (x0 - 1) & MASK;
        const int rC = x0, rN = x0 + 1;
        float4 sA[3];
        float plw[3], prx[3];
        #pragma unroll
        for (int c = 0; c < 3; ++c) {
            const float* cp = sb + ((long)c << 18);
            sA[c] = *(const float4*)(cp + ((long)rA << 9) + yo);
            sP[c] = *(const float4*)(cp + ((long)rP << 9) + yo);
            sC[c] = *(const float4*)(cp + ((long)rC << 9) + yo);
            sN[c] = *(const float4*)(cp + ((long)rN << 9) + yo);
            plw[c]  = cp[((long)rP << 9) + ym1];  prx[c]  = cp[((long)rP << 9) + yp4];
            sClw[c] = cp[((long)rC << 9) + ym1];  sCrx[c] = cp[((long)rC << 9) + yp4];
            sNlw[c] = cp[((long)rN << 9) + ym1];  sNrx[c] = cp[((long)rN << 9) + yp4];
        }

        bP = make_float4(0.f, 0.f, 0.f, 0.f);
        #pragma unroll
        for (int c = 0; c < 3; ++c)
            bP = fma4(sP[c], sA[c] + sC[c] + ymv(sP[c], plw[c]) + ypv(sP[c], prx[c]), bP);

        bC = make_float4(0.f, 0.f, 0.f, 0.f);
        #pragma unroll
        for (int c = 0; c < 3; ++c)
            bC = fma4(sC[c], sP[c] + sN[c] + ymv(sC[c], sClw[c]) + ypv(sC[c], sCrx[c]), bC);

        bw[1][t] = bC.w; bx[1][t] = bC.x;
        __syncthreads();
        bClw = bw[1][tm]; bCrx = bx[1][tp];
    }

    // ---------------- Main loop: 2 rows per iteration ----------------
    #pragma unroll 2
    for (int i = 0; i < XCHUNK / 2; ++i) {
        const int x = x0 + 2 * i;
        const int p = i & 1;
        const int s2 = (x + 2) % NSLOT, s3 = (x + 3) % NSLOT;

        // 1. prefetch rows x+4, x+5 (one group)
        {
            const int r4 = (x + 4) & MASK, r5 = (x + 5) & MASK;
            #pragma unroll
            for (int c = 0; c < 3; ++c) {
                cpa16(&ring[(x + 4) % NSLOT][c][yo], sb + ((long)c << 18) + ((long)r4 << 9) + yo);
                cpa16(&ring[(x + 5) % NSLOT][c][yo], sb + ((long)c << 18) + ((long)r5 << 9) + yo);
            }
            cpa_commit();
        }

        // 2. wait: rows x+2, x+3 landed (own vectors readable by issuing thread)
        cpa_wait1();
        float4 sN2[3], sN3[3];
        #pragma unroll
        for (int c = 0; c < 3; ++c) {
            sN2[c] = *(const float4*)&ring[s2][c][yo];
            sN3[c] = *(const float4*)&ring[s3][c][yo];
        }

        // 3. bN = b(x+1)
        float4 bN = make_float4(0.f, 0.f, 0.f, 0.f);
        #pragma unroll
        for (int c = 0; c < 3; ++c)
            bN = fma4(sN[c], sC[c] + sN2[c] + ymv(sN[c], sNlw[c]) + ypv(sN[c], sNrx[c]), bN);

        // 4. publish bN bounds
        bw[p][t] = bN.w; bx[p][t] = bN.x;

        // 5. F(x)  (all inputs pre-barrier)
        {
            const float4 bym = ymv(bC, bClw);
            const float4 byp = ypv(bC, bCrx);
            float4 Fv[3];
            #pragma unroll
            for (int c = 0; c < 3; ++c) {
                const float4 ymc = ymv(sC[c], sClw[c]);
                const float4 ypc = ypv(sC[c], sCrx[c]);
                const float4 Fs  = sP[c] + sN[c] + ymc + ypc;
                const float4 Fbs = fma4(sP[c], bP,
                                   fma4(sN[c], bN,
                                   fma4(ymc, bym,
                                        make_float4(ypc.x * byp.x, ypc.y * byp.y,
                                                    ypc.z * byp.z, ypc.w * byp.w))));
                Fv[c] = fma4(Fs, bC, Fbs);
            }
            float* op = out + base + (((long)x) << 9) + yo;
            __stcs((float4*)(op),              scale4(coeff, crossm(sC[1], Fv[2], sC[2], Fv[1])));
            __stcs((float4*)(op + (1L << 18)), scale4(coeff, crossm(sC[2], Fv[0], sC[0], Fv[2])));
            __stcs((float4*)(op + (2L << 18)), scale4(coeff, crossm(sC[0], Fv[1], sC[1], Fv[0])));
        }

        __syncthreads();

        // 6. post-barrier: bN bounds + ring halo scalars
        const float bNlw = bw[p][tm], bNrx = bx[p][tp];
        float n2lw[3], n2rx[3], n3lw[3], n3rx[3];
        float bN2lw = 0.f, bN2rx = 0.f;
        #pragma unroll
        for (int c = 0; c < 3; ++c) {
            n2lw[c] = ring[s2][c][ym1];
            n2rx[c] = ring[s2][c][yp4];
            n3lw[c] = ring[s3][c][ym1];
            n3rx[c] = ring[s3][c][yp4];
            const float l2 = ring[s2][c][ym2];
            const float r5v = ring[s2][c][yp5];
            bN2lw = fmaf(n2lw[c], sNlw[c] + n3lw[c] + l2 + sN2[c].x, bN2lw);
            bN2rx = fmaf(n2rx[c], sNrx[c] + n3rx[c] + r5v + sN2[c].w, bN2rx);
        }

        // 7. bN2 = b(x+2)
        float4 bN2 = make_float4(0.f, 0.f, 0.f, 0.f);
        #pragma unroll
        for (int c = 0; c < 3; ++c)
            bN2 = fma4(sN2[c], sN[c] + sN3[c] + ymv(sN2[c], n2lw[c]) + ypv(sN2[c], n2rx[c]), bN2);

        // 8. F(x+1)
        {
            const float4 bym = ymv(bN, bNlw);
            const float4 byp = ypv(bN, bNrx);
            float4 Fv[3];
            #pragma unroll
            for (int c = 0; c < 3; ++c) {
                const float4 ymc = ymv(sN[c], sNlw[c]);
                const float4 ypc = ypv(sN[c], sNrx[c]);
                const float4 Fs  = sC[c] + sN2[c] + ymc + ypc;
                const float4 Fbs = fma4(sC[c], bC,
                                   fma4(sN2[c], bN2,
                                   fma4(ymc, bym,
                                        make_float4(ypc.x * byp.x, ypc.y * byp.y,
                                                    ypc.z * byp.z, ypc.w * byp.w))));
                Fv[c] = fma4(Fs, bN, Fbs);
            }
            float* op = out + base + (((long)(x + 1)) << 9) + yo;
            __stcs((float4*)(op),              scale4(coeff, crossm(sN[1], Fv[2], sN[2], Fv[1])));
            __stcs((float4*)(op + (1L << 18)), scale4(coeff, crossm(sN[2], Fv[0], sN[0], Fv[2])));
            __stcs((float4*)(op + (2L << 18)), scale4(coeff, crossm(sN[0], Fv[1], sN[1], Fv[0])));
        }

        // 9. rotate by 2 rows (renames under unroll 2)
        #pragma unroll
        for (int c = 0; c < 3; ++c) {
            sP[c] = sN[c]; sC[c] = sN2[c]; sN[c] = sN3[c];
            sClw[c] = n2lw[c]; sCrx[c] = n2rx[c];
            sNlw[c] = n3lw[c]; sNrx[c] = n3rx[c];
        }
        bP = bN; bC = bN2;
        bClw = bN2lw; bCrx = bN2rx;
    }
}

extern "C" void kernel_launch(void* const* d_in, const int* in_sizes, int n_in,
                              void* d_out, int out_size)
{
    const float* s  = (const float*)d_in[0];
    const float* t  = (const float*)d_in[1];
    const float* c0 = (const float*)d_in[2];
    float* out = (float*)d_out;

    dim3 grid(512 / XCHUNK, 32);   // 16 x-strips * 32 batches = 512 blocks
    psi11t_kernel<<<grid, NTH>>>(s, t, c0, out);
}

// round 13
// speedup vs baseline: 1.1644x; 1.0437x over previous
#include <cuda_runtime.h>
#include <cstdint>

// Psi11t flow force: F = 2*t*c0 * ( s x (Fs*b + Fbs) )
//   Fs = nbr4(s), b = s.Fs, Fbs = nbr4(s*b). Periodic 512x512, B=32, S=3.
// R12 skeleton (cp.async 6-slot ring, 2 rows/iter, 1 barrier) + algebra:
//   Fv_c = sum_nbr s_nbr_c * (b_center + b_nbr)   [b pre-scaled by coeff]
// which removes the Fs accumulation and the output scaling.

#define MASK 511
#define XCHUNK 32
#define NTH 128
#define NSLOT 6

__device__ __forceinline__ float4 operator+(float4 a, float4 b) {
    return make_float4(a.x + b.x, a.y + b.y, a.z + b.z, a.w + b.w);
}
__device__ __forceinline__ float4 fma4(float4 a, float4 b, float4 c) {
    return make_float4(fmaf(a.x, b.x, c.x), fmaf(a.y, b.y, c.y),
                       fmaf(a.z, b.z, c.z), fmaf(a.w, b.w, c.w));
}
__device__ __forceinline__ float4 mul4(float4 a, float4 b) {
    return make_float4(a.x * b.x, a.y * b.y, a.z * b.z, a.w * b.w);
}
__device__ __forceinline__ float4 crossm(float4 a, float4 b, float4 c, float4 d) {
    return make_float4(fmaf(a.x, b.x, -(c.x * d.x)), fmaf(a.y, b.y, -(c.y * d.y)),
                       fmaf(a.z, b.z, -(c.z * d.z)), fmaf(a.w, b.w, -(c.w * d.w)));
}
__device__ __forceinline__ float4 ymv(float4 a, float lw) {
    return make_float4(lw, a.x, a.y, a.z);
}
__device__ __forceinline__ float4 ypv(float4 a, float rx) {
    return make_float4(a.y, a.z, a.w, rx);
}
__device__ __forceinline__ float4 scale4(float k, float4 a) {
    return make_float4(k * a.x, k * a.y, k * a.z, k * a.w);
}
__device__ __forceinline__ void cpa16(float* smem_dst, const float* g) {
    uint32_t sa = (uint32_t)__cvta_generic_to_shared(smem_dst);
    asm volatile("cp.async.cg.shared.global [%0], [%1], 16;" :: "r"(sa), "l"(g));
}
__device__ __forceinline__ void cpa_commit() {
    asm volatile("cp.async.commit_group;");
}
__device__ __forceinline__ void cpa_wait1() {
    asm volatile("cp.async.wait_group 1;");
}

__global__ __launch_bounds__(NTH, 4) void psi11t_kernel(
    const float* __restrict__ s,
    const float* __restrict__ tt,
    const float* __restrict__ c0,
    float* __restrict__ out)
{
    __shared__ float ring[NSLOT][3][512];   // 36864 B
    __shared__ float bw[2][NTH], bx[2][NTH];

    const int bb = blockIdx.y;
    const int x0 = blockIdx.x * XCHUNK;
    const int t  = threadIdx.x;
    const int tm = (t - 1) & (NTH - 1);
    const int tp = (t + 1) & (NTH - 1);
    const long base = (long)bb * (3L << 18);
    const float* sb = s + base;
    const int yo  = 4 * t;
    const int ym1 = (yo - 1) & MASK;
    const int ym2 = (yo - 2) & MASK;
    const int yp4 = (yo + 4) & MASK;
    const int yp5 = (yo + 5) & MASK;

    const float coeff = 2.0f * tt[0] * c0[0];

    // ---- prologue prefetch: rows x0+2, x0+3 as ONE group ----
    {
        const int r2 = (x0 + 2) & MASK, r3 = (x0 + 3) & MASK;
        #pragma unroll
        for (int c = 0; c < 3; ++c) {
            cpa16(&ring[(x0 + 2) % NSLOT][c][yo], sb + ((long)c << 18) + ((long)r2 << 9) + yo);
            cpa16(&ring[(x0 + 3) % NSLOT][c][yo], sb + ((long)c << 18) + ((long)r3 << 9) + yo);
        }
        cpa_commit();
    }

    // Persistent: s rows x-1,x,x+1; b rows x-1,x (pre-scaled by coeff); bounds.
    float4 sP[3], sC[3], sN[3];
    float4 bP, bC;
    float  sClw[3], sCrx[3], sNlw[3], sNrx[3];
    float  bClw, bCrx;

    // ---------------- Prologue compute: rows x0-2 .. x0+1 (direct LDG) -------
    {
        const int rA = (x0 - 2) & MASK, rP = (x0 - 1) & MASK;
        const int rC = x0, rN = x0 + 1;
        float4 sA[3];
        float plw[3], prx[3];
        #pragma unroll
        for (int c = 0; c < 3; ++c) {
            const float* cp = sb + ((long)c << 18);
            sA[c] = *(const float4*)(cp + ((long)rA << 9) + yo);
            sP[c] = *(const float4*)(cp + ((long)rP << 9) + yo);
            sC[c] = *(const float4*)(cp + ((long)rC << 9) + yo);
            sN[c] = *(const float4*)(cp + ((long)rN << 9) + yo);
            plw[c]  = cp[((long)rP << 9) + ym1];  prx[c]  = cp[((long)rP << 9) + yp4];
            sClw[c] = cp[((long)rC << 9) + ym1];  sCrx[c] = cp[((long)rC << 9) + yp4];
            sNlw[c] = cp[((long)rN << 9) + ym1];  sNrx[c] = cp[((long)rN << 9) + yp4];
        }

        bP = make_float4(0.f, 0.f, 0.f, 0.f);
        #pragma unroll
        for (int c = 0; c < 3; ++c)
            bP = fma4(sP[c], sA[c] + sC[c] + ymv(sP[c], plw[c]) + ypv(sP[c], prx[c]), bP);
        bP = scale4(coeff, bP);

        bC = make_float4(0.f, 0.f, 0.f, 0.f);
        #pragma unroll
        for (int c = 0; c < 3; ++c)
            bC = fma4(sC[c], sP[c] + sN[c] + ymv(sC[c], sClw[c]) + ypv(sC[c], sCrx[c]), bC);
        bC = scale4(coeff, bC);

        bw[1][t] = bC.w; bx[1][t] = bC.x;
        __syncthreads();
        bClw = bw[1][tm]; bCrx = bx[1][tp];
    }

    // ---------------- Main loop: 2 rows per iteration ----------------
    #pragma unroll 2
    for (int i = 0; i < XCHUNK / 2; ++i) {
        const int x = x0 + 2 * i;
        const int p = i & 1;
        const int s2 = (x + 2) % NSLOT, s3 = (x + 3) % NSLOT;

        // 1. prefetch rows x+4, x+5 (one group)
        {
            const int r4 = (x + 4) & MASK, r5 = (x + 5) & MASK;
            #pragma unroll
            for (int c = 0; c < 3; ++c) {
                cpa16(&ring[(x + 4) % NSLOT][c][yo], sb + ((long)c << 18) + ((long)r4 << 9) + yo);
                cpa16(&ring[(x + 5) % NSLOT][c][yo], sb + ((long)c << 18) + ((long)r5 << 9) + yo);
            }
            cpa_commit();
        }

        // 2. wait: rows x+2, x+3 landed
        cpa_wait1();
        float4 sN2[3], sN3[3];
        #pragma unroll
        for (int c = 0; c < 3; ++c) {
            sN2[c] = *(const float4*)&ring[s2][c][yo];
            sN3[c] = *(const float4*)&ring[s3][c][yo];
        }

        // 3. bN = coeff * b(x+1)
        float4 bN = make_float4(0.f, 0.f, 0.f, 0.f);
        #pragma unroll
        for (int c = 0; c < 3; ++c)
            bN = fma4(sN[c], sC[c] + sN2[c] + ymv(sN[c], sNlw[c]) + ypv(sN[c], sNrx[c]), bN);
        bN = scale4(coeff, bN);

        // 4. publish bN bounds
        bw[p][t] = bN.w; bx[p][t] = bN.x;

        // 5. F(x): Fv_c = sum_nbr s_nbr_c * (bC + b_nbr)
        {
            const float4 wxm = bC + bP;
            const float4 wxp = bC + bN;
            const float4 wym = bC + ymv(bC, bClw);
            const float4 wyp = bC + ypv(bC, bCrx);
            float4 Fv[3];
            #pragma unroll
            for (int c = 0; c < 3; ++c) {
                const float4 ymc = ymv(sC[c], sClw[c]);
                const float4 ypc = ypv(sC[c], sCrx[c]);
                Fv[c] = fma4(sP[c], wxm,
                        fma4(sN[c], wxp,
                        fma4(ymc, wym, mul4(ypc, wyp))));
            }
            float* op = out + base + (((long)x) << 9) + yo;
            __stcs((float4*)(op),              crossm(sC[1], Fv[2], sC[2], Fv[1]));
            __stcs((float4*)(op + (1L << 18)), crossm(sC[2], Fv[0], sC[0], Fv[2]));
            __stcs((float4*)(op + (2L << 18)), crossm(sC[0], Fv[1], sC[1], Fv[0]));
        }

        __syncthreads();

        // 6. post-barrier: bN bounds + ring halo scalars; recompute bN2 edges
        const float bNlw = bw[p][tm], bNrx = bx[p][tp];
        float n2lw[3], n2rx[3], n3lw[3], n3rx[3];
        float bN2lw = 0.f, bN2rx = 0.f;
        #pragma unroll
        for (int c = 0; c < 3; ++c) {
            n2lw[c] = ring[s2][c][ym1];
            n2rx[c] = ring[s2][c][yp4];
            n3lw[c] = ring[s3][c][ym1];
            n3rx[c] = ring[s3][c][yp4];
            const float l2 = ring[s2][c][ym2];
            const float r5v = ring[s2][c][yp5];
            bN2lw = fmaf(n2lw[c], sNlw[c] + n3lw[c] + l2 + sN2[c].x, bN2lw);
            bN2rx = fmaf(n2rx[c], sNrx[c] + n3rx[c] + r5v + sN2[c].w, bN2rx);
        }
        bN2lw *= coeff; bN2rx *= coeff;

        // 7. bN2 = coeff * b(x+2)
        float4 bN2 = make_float4(0.f, 0.f, 0.f, 0.f);
        #pragma unroll
        for (int c = 0; c < 3; ++c)
            bN2 = fma4(sN2[c], sN[c] + sN3[c] + ymv(sN2[c], n2lw[c]) + ypv(sN2[c], n2rx[c]), bN2);
        bN2 = scale4(coeff, bN2);

        // 8. F(x+1)
        {
            const float4 wxm = bN + bC;
            const float4 wxp = bN + bN2;
            const float4 wym = bN + ymv(bN, bNlw);
            const float4 wyp = bN + ypv(bN, bNrx);
            float4 Fv[3];
            #pragma unroll
            for (int c = 0; c < 3; ++c) {
                const float4 ymc = ymv(sN[c], sNlw[c]);
                const float4 ypc = ypv(sN[c], sNrx[c]);
                Fv[c] = fma4(sC[c], wxm,
                        fma4(sN2[c], wxp,
                        fma4(ymc, wym, mul4(ypc, wyp))));
            }
            float* op = out + base + (((long)(x + 1)) << 9) + yo;
            __stcs((float4*)(op),              crossm(sN[1], Fv[2], sN[2], Fv[1]));
            __stcs((float4*)(op + (1L << 18)), crossm(sN[2], Fv[0], sN[0], Fv[2]));
            __stcs((float4*)(op + (2L << 18)), crossm(sN[0], Fv[1], sN[1], Fv[0]));
        }

        // 9. rotate by 2 rows
        #pragma unroll
        for (int c = 0; c < 3; ++c) {
            sP[c] = sN[c]; sC[c] = sN2[c]; sN[c] = sN3[c];
            sClw[c] = n2lw[c]; sCrx[c] = n2rx[c];
            sNlw[c] = n3lw[c]; sNrx[c] = n3rx[c];
        }
        bP = bN; bC = bN2;
        bClw = bN2lw; bCrx = bN2rx;
    }
}

extern "C" void kernel_launch(void* const* d_in, const int* in_sizes, int n_in,
                              void* d_out, int out_size)
{
    const float* s  = (const float*)d_in[0];
    const float* t  = (const float*)d_in[1];
    const float* c0 = (const float*)d_in[2];
    float* out = (float*)d_out;

    dim3 grid(512 / XCHUNK, 32);   // 16 x-strips * 32 batches = 512 blocks
    psi11t_kernel<<<grid, NTH>>>(s, t, c0, out);
}